// round 1
// baseline (speedup 1.0000x reference)
#include <cuda_runtime.h>

// Problem constants
namespace {
constexpr int B_  = 4;
constexpr int C_  = 128;
constexpr int N_  = 1024;
constexpr int KNN = 20;
constexpr int M_  = 4096;   // N*UP
constexpr int OC  = 512;    // edge-conv out channels
constexpr int CH  = 130;    // net channels after grid concat
constexpr int CF  = 32;     // f/g channels
constexpr int MID = 256;    // W1 out
constexpr int RO  = 128;    // W2 out
}
#define EPS_ 1e-5f
#define NEGINF_ -3.4e38f

// ---- scratch (device globals; no allocations allowed) ----
__device__ float d_sq   [B_*N_];
__device__ float d_negd [B_*N_*N_];
__device__ int   d_idx  [B_*N_*KNN];
__device__ float d_Yt   [B_*N_*OC];    // [b][n][o]
__device__ float d_baset[B_*N_*OC];    // [b][n][o]
__device__ float d_st1p [2*64*OC];     // per-block partial sums (deterministic)
__device__ float d_st1  [2*OC];
__device__ float d_net3 [B_*CH*M_];    // [b][c][m]
__device__ float d_fr   [B_*CF*M_];
__device__ float d_gr   [B_*CF*M_];
__device__ float d_hr   [B_*CH*M_];
__device__ float d_st2  [2*(CF+CF+CH)];
__device__ float d_fn   [B_*CF*M_];
__device__ float d_gn   [B_*CF*M_];
__device__ float d_hn   [B_*CH*M_];
__device__ float d_s    [(size_t)B_*M_*M_];   // 268 MB attention matrix
__device__ float d_o    [B_*CH*M_];
__device__ float d_n4   [B_*CH*M_];
__device__ float d_y1   [B_*MID*M_];

// ---------------- 1) per-point squared norms ----------------
__global__ void k_sq(const float* __restrict__ x) {
    int t = blockIdx.x * 256 + threadIdx.x;      // B*N = 4096
    int b = t >> 10, n = t & 1023;
    const float* xb = x + b * C_ * N_ + n;
    float s = 0.f;
#pragma unroll 8
    for (int c = 0; c < C_; c++) { float v = xb[c * N_]; s = fmaf(v, v, s); }
    d_sq[t] = s;
}

// ---------------- 2) neg squared distance: 2 x^T x - sq_n - sq_m ----------------
__global__ void k_negd(const float* __restrict__ x) {
    int b = blockIdx.z;
    int n0 = blockIdx.y * 64, m0 = blockIdx.x * 64;
    __shared__ float As[32][64];
    __shared__ float Bs[32][64];
    int tid = threadIdx.x;
    const float* xb = x + b * C_ * N_;
    float acc[4][4] = {};
    for (int k0 = 0; k0 < C_; k0 += 32) {
        for (int e = tid; e < 32 * 64; e += 256) {
            int k = e >> 6, i = e & 63;
            As[k][i] = xb[(k0 + k) * N_ + n0 + i];
            Bs[k][i] = xb[(k0 + k) * N_ + m0 + i];
        }
        __syncthreads();
        int ty = tid >> 4, tx = tid & 15;
#pragma unroll
        for (int k = 0; k < 32; k++) {
            float4 a = *(const float4*)&As[k][ty * 4];
            float4 bv = *(const float4*)&Bs[k][tx * 4];
            float av[4] = {a.x, a.y, a.z, a.w};
            float bb[4] = {bv.x, bv.y, bv.z, bv.w};
#pragma unroll
            for (int i = 0; i < 4; i++)
#pragma unroll
                for (int j = 0; j < 4; j++) acc[i][j] = fmaf(av[i], bb[j], acc[i][j]);
        }
        __syncthreads();
    }
    int ty = tid >> 4, tx = tid & 15;
#pragma unroll
    for (int i = 0; i < 4; i++) {
        int n = n0 + ty * 4 + i;
        float sn = d_sq[b * N_ + n];
        float4 o;
        o.x = 2.f * acc[i][0] - sn - d_sq[b * N_ + m0 + tx * 4 + 0];
        o.y = 2.f * acc[i][1] - sn - d_sq[b * N_ + m0 + tx * 4 + 1];
        o.z = 2.f * acc[i][2] - sn - d_sq[b * N_ + m0 + tx * 4 + 2];
        o.w = 2.f * acc[i][3] - sn - d_sq[b * N_ + m0 + tx * 4 + 3];
        *(float4*)&d_negd[(b * N_ + n) * N_ + m0 + tx * 4] = o;
    }
}

// ---------------- 3) top-k (k=20) per row, tie -> lower index ----------------
__global__ void k_topk() {
    int bn = blockIdx.x;                  // b*N + n
    __shared__ float vals[N_];
    __shared__ float rv[256];
    __shared__ int   ri[256];
    int tid = threadIdx.x;
    const float* row = &d_negd[(size_t)bn * N_];
    for (int i = tid; i < N_; i += 256) vals[i] = row[i];
    __syncthreads();
    for (int t = 0; t < KNN; t++) {
        float bv = NEGINF_; int bi = 0;
        for (int i = tid; i < N_; i += 256) {
            float v = vals[i];
            if (v > bv || (v == bv && i < bi)) { bv = v; bi = i; }
        }
        rv[tid] = bv; ri[tid] = bi;
        __syncthreads();
        for (int s = 128; s > 0; s >>= 1) {
            if (tid < s) {
                float v2 = rv[tid + s]; int i2 = ri[tid + s];
                if (v2 > rv[tid] || (v2 == rv[tid] && i2 < ri[tid])) { rv[tid] = v2; ri[tid] = i2; }
            }
            __syncthreads();
        }
        if (tid == 0) { d_idx[bn * KNN + t] = ri[0]; vals[ri[0]] = NEGINF_; }
        __syncthreads();
    }
}

// ---------------- 4) Y = Wa@x, base = (Wb-Wa)@x, both point-major ----------------
__global__ void k_yb(const float* __restrict__ x, const float* __restrict__ Wec) {
    int b = blockIdx.z;
    int n0 = blockIdx.y * 64;   // 16
    int o0 = blockIdx.x * 64;   // 8
    __shared__ float Xs[32][64];
    __shared__ float Was[32][64];
    __shared__ float Wbs[32][64];
    int tid = threadIdx.x;
    float a1[4][4] = {}, a2[4][4] = {};
    for (int k0 = 0; k0 < C_; k0 += 32) {
        for (int e = tid; e < 32 * 64; e += 256) {
            int k = e >> 6, i = e & 63;
            Xs[k][i] = x[b * C_ * N_ + (k0 + k) * N_ + n0 + i];
            float wa = Wec[(o0 + i) * 256 + k0 + k];
            float wb = Wec[(o0 + i) * 256 + 128 + k0 + k];
            Was[k][i] = wa;
            Wbs[k][i] = wb - wa;
        }
        __syncthreads();
        int ty = tid >> 4, tx = tid & 15;   // ty -> n, tx -> o
#pragma unroll
        for (int k = 0; k < 32; k++) {
            float4 xa = *(const float4*)&Xs[k][ty * 4];
            float4 wa = *(const float4*)&Was[k][tx * 4];
            float4 wb = *(const float4*)&Wbs[k][tx * 4];
            float xv[4] = {xa.x, xa.y, xa.z, xa.w};
            float wav[4] = {wa.x, wa.y, wa.z, wa.w};
            float wbv[4] = {wb.x, wb.y, wb.z, wb.w};
#pragma unroll
            for (int i = 0; i < 4; i++)
#pragma unroll
                for (int j = 0; j < 4; j++) {
                    a1[i][j] = fmaf(xv[i], wav[j], a1[i][j]);
                    a2[i][j] = fmaf(xv[i], wbv[j], a2[i][j]);
                }
        }
        __syncthreads();
    }
    int ty = tid >> 4, tx = tid & 15;
#pragma unroll
    for (int i = 0; i < 4; i++) {
        int n = n0 + ty * 4 + i;
        *(float4*)&d_Yt   [(b * N_ + n) * OC + o0 + tx * 4] = make_float4(a1[i][0], a1[i][1], a1[i][2], a1[i][3]);
        *(float4*)&d_baset[(b * N_ + n) * OC + o0 + tx * 4] = make_float4(a2[i][0], a2[i][1], a2[i][2], a2[i][3]);
    }
}

// ---------------- 5) BN stats for edge-conv (deterministic partials) ----------------
__global__ void k_stats1() {
    int b = blockIdx.y;
    int nc = blockIdx.x;            // 16 chunks of 64 points
    int p = b * 16 + nc;
    int o = threadIdx.x;            // 512
    __shared__ int sidx[64 * KNN];
    for (int e = threadIdx.x; e < 64 * KNN; e += 512)
        sidx[e] = d_idx[(b * N_ + nc * 64) * KNN + e];
    __syncthreads();
    float s = 0.f, ss = 0.f;
    for (int nn = 0; nn < 64; nn++) {
        int n = nc * 64 + nn;
        float bv = d_baset[(b * N_ + n) * OC + o];
#pragma unroll
        for (int k = 0; k < KNN; k++) {
            int j = sidx[nn * KNN + k];
            float v = d_Yt[(b * N_ + j) * OC + o] + bv;
            s += v; ss = fmaf(v, v, ss);
        }
    }
    d_st1p[p * OC + o] = s;
    d_st1p[(64 + p) * OC + o] = ss;
}

__global__ void k_red1() {
    int o = blockIdx.x * 256 + threadIdx.x;
    if (o >= OC) return;
    float s = 0.f, ss = 0.f;
    for (int p = 0; p < 64; p++) { s += d_st1p[p * OC + o]; ss += d_st1p[(64 + p) * OC + o]; }
    d_st1[o] = s; d_st1[OC + o] = ss;
}

// ---------------- 6) normalize + leaky + max over k, write reshaped net3 ----------------
__global__ void k_edgemax(const float* __restrict__ g_ec, const float* __restrict__ b_ec) {
    int bn = blockIdx.x;
    int b = bn >> 10, n = bn & 1023;
    __shared__ int sidx[KNN];
    int tid = threadIdx.x;
    if (tid < KNN) sidx[tid] = d_idx[bn * KNN + tid];
    __syncthreads();
    const float cnt = (float)(B_ * N_ * KNN);
    for (int o = tid; o < OC; o += 256) {
        float mean = d_st1[o] / cnt;
        float var  = d_st1[OC + o] / cnt - mean * mean;
        float sc = rsqrtf(var + EPS_) * g_ec[o];
        float sh = b_ec[o] - mean * sc;
        float bv = d_baset[bn * OC + o];
        float best = NEGINF_;
#pragma unroll
        for (int k = 0; k < KNN; k++) {
            float v = d_Yt[(b * N_ + sidx[k]) * OC + o] + bv;
            v = fmaf(v, sc, sh);
            v = v > 0.f ? v : 0.2f * v;
            best = fmaxf(best, v);
        }
        int u = o >> 7, c = o & 127;
        d_net3[(b * CH + c) * M_ + n * 4 + u] = best;
    }
}

__global__ void k_grid() {
    int t = blockIdx.x * 256 + threadIdx.x;   // B*M = 16384
    int b = t >> 12, m = t & 4095;
    int gi = m >> 10;
    float gx = (gi < 2) ? -0.2f : 0.2f;
    float gy = (gi & 1) ? 0.2f : -0.2f;
    d_net3[(b * CH + 128) * M_ + m] = gx;
    d_net3[(b * CH + 129) * M_ + m] = gy;
}

// ---------------- 7) f/g/h raw convs (K=130) ----------------
__global__ void k_fgh(const float* __restrict__ Wf, const float* __restrict__ bf,
                      const float* __restrict__ Wg, const float* __restrict__ bg,
                      const float* __restrict__ Wh, const float* __restrict__ bh) {
    int b = blockIdx.y, m0 = blockIdx.x * 64;
    __shared__ float In[CH][64];
    int tid = threadIdx.x;
    for (int e = tid; e < CH * 64; e += 256) {
        int k = e >> 6, i = e & 63;
        In[k][i] = d_net3[(b * CH + k) * M_ + m0 + i];
    }
    __syncthreads();
    int ml = tid & 63, rq = tid >> 6;
    for (int r = rq; r < 194; r += 4) {
        const float* W; float bias; float* outp;
        if (r < 32)      { W = Wf + r * CH;        bias = bf[r];      outp = &d_fr[(b * CF + r) * M_]; }
        else if (r < 64) { int c = r - 32; W = Wg + c * CH; bias = bg[c]; outp = &d_gr[(b * CF + c) * M_]; }
        else             { int c = r - 64; W = Wh + c * CH; bias = bh[c]; outp = &d_hr[(b * CH + c) * M_]; }
        float acc = bias;
#pragma unroll 10
        for (int k = 0; k < CH; k++) acc = fmaf(W[k], In[k][ml], acc);
        outp[m0 + ml] = acc;
    }
}

// ---------------- 8) BN stats for f/g/h (one block per channel) ----------------
__global__ void k_stats2() {
    int ch = blockIdx.x, tid = threadIdx.x;   // 194 channels
    __shared__ float r1[256], r2[256];
    float s = 0.f, ss = 0.f;
    for (int b = 0; b < B_; b++) {
        const float* p;
        if (ch < 32)      p = &d_fr[(b * CF + ch) * M_];
        else if (ch < 64) p = &d_gr[(b * CF + (ch - 32)) * M_];
        else              p = &d_hr[(b * CH + (ch - 64)) * M_];
        for (int m = tid; m < M_; m += 256) { float v = p[m]; s += v; ss = fmaf(v, v, ss); }
    }
    r1[tid] = s; r2[tid] = ss;
    __syncthreads();
    for (int st = 128; st > 0; st >>= 1) {
        if (tid < st) { r1[tid] += r1[tid + st]; r2[tid] += r2[tid + st]; }
        __syncthreads();
    }
    if (tid == 0) { d_st2[ch] = r1[0]; d_st2[194 + ch] = r2[0]; }
}

// ---------------- 9) normalize + relu (sel: 0=f, 1=g, 2=h) ----------------
__global__ void k_norm2(int sel, const float* __restrict__ gamma, const float* __restrict__ beta) {
    int t = blockIdx.x * 256 + threadIdx.x;
    int Cdim = (sel == 2) ? CH : CF;
    int total = B_ * Cdim * M_;
    if (t >= total) return;
    int c = (t / M_) % Cdim;
    int off = (sel == 0) ? 0 : (sel == 1) ? 32 : 64;
    const float cntf = (float)(B_ * M_);
    float mean = d_st2[off + c] / cntf;
    float var  = d_st2[194 + off + c] / cntf - mean * mean;
    float sc = rsqrtf(var + EPS_) * gamma[c];
    float sh = beta[c] - mean * sc;
    const float* raw = (sel == 0) ? d_fr : (sel == 1) ? d_gr : d_hr;
    float* outp      = (sel == 0) ? d_fn : (sel == 1) ? d_gn : d_hn;
    outp[t] = fmaxf(fmaf(raw[t], sc, sh), 0.f);
}

// ---------------- 10) s[b,m,n] = sum_c g[c,m] f[c,n]  (K=32) ----------------
__global__ void k_sgemm() {
    int b = blockIdx.z;
    int m0 = blockIdx.y * 64, n0 = blockIdx.x * 64;
    __shared__ float Gs[CF][64];
    __shared__ float Fs[CF][64];
    int tid = threadIdx.x;
    for (int e = tid; e < CF * 64; e += 256) {
        int k = e >> 6, i = e & 63;
        Gs[k][i] = d_gn[(b * CF + k) * M_ + m0 + i];
        Fs[k][i] = d_fn[(b * CF + k) * M_ + n0 + i];
    }
    __syncthreads();
    int ty = tid >> 4, tx = tid & 15;
    float acc[4][4] = {};
#pragma unroll
    for (int k = 0; k < CF; k++) {
        float4 a = *(const float4*)&Gs[k][ty * 4];
        float4 bv = *(const float4*)&Fs[k][tx * 4];
        float av[4] = {a.x, a.y, a.z, a.w};
        float bb[4] = {bv.x, bv.y, bv.z, bv.w};
#pragma unroll
        for (int i = 0; i < 4; i++)
#pragma unroll
            for (int j = 0; j < 4; j++) acc[i][j] = fmaf(av[i], bb[j], acc[i][j]);
    }
#pragma unroll
    for (int i = 0; i < 4; i++) {
        int m = m0 + ty * 4 + i;
        *(float4*)&d_s[((size_t)(b * M_ + m)) * M_ + n0 + tx * 4] =
            make_float4(acc[i][0], acc[i][1], acc[i][2], acc[i][3]);
    }
}

// ---------------- 11) row softmax (axis=2), in place ----------------
__global__ void k_softmax() {
    int bm = blockIdx.x;     // B*M rows
    __shared__ float row[M_];
    __shared__ float red[256];
    float* src = &d_s[(size_t)bm * M_];
    int tid = threadIdx.x;
    float mx = NEGINF_;
    for (int i = tid; i < M_; i += 256) { float v = src[i]; row[i] = v; mx = fmaxf(mx, v); }
    red[tid] = mx;
    __syncthreads();
    for (int s = 128; s > 0; s >>= 1) { if (tid < s) red[tid] = fmaxf(red[tid], red[tid + s]); __syncthreads(); }
    mx = red[0];
    __syncthreads();
    float sum = 0.f;
    for (int i = tid; i < M_; i += 256) { float e = __expf(row[i] - mx); row[i] = e; sum += e; }
    red[tid] = sum;
    __syncthreads();
    for (int s = 128; s > 0; s >>= 1) { if (tid < s) red[tid] += red[tid + s]; __syncthreads(); }
    float inv = 1.f / red[0];
    __syncthreads();
    for (int i = tid; i < M_; i += 256) src[i] = row[i] * inv;
}

// ---------------- 12) o[b,c,m] = sum_j h[c,j] * beta[j,m]  (the FLOP wall) ----------------
__global__ void k_ogemm() {
    int b = blockIdx.y;
    int m0 = blockIdx.x * 64;
    __shared__ float Bs[16][64];
    __shared__ float Hs[16][144];
    int tid = threadIdx.x;
    int mi = tid & 15, ci = tid >> 4;   // mi -> 4 m's, ci + 16r -> c
    float acc[9][4] = {};
    for (int j0 = 0; j0 < M_; j0 += 16) {
        {
            int k = tid >> 4, c4 = tid & 15;
            *(float4*)&Bs[k][c4 * 4] =
                *(const float4*)&d_s[((size_t)(b * M_ + j0 + k)) * M_ + m0 + c4 * 4];
        }
        for (int e = tid; e < 16 * 144; e += 256) {
            int c = e >> 4, k = e & 15;
            Hs[k][c] = (c < CH) ? d_hn[(b * CH + c) * M_ + j0 + k] : 0.f;
        }
        __syncthreads();
#pragma unroll
        for (int k = 0; k < 16; k++) {
            float4 bv = *(const float4*)&Bs[k][mi * 4];
#pragma unroll
            for (int r = 0; r < 9; r++) {
                float hv = Hs[k][ci + 16 * r];
                acc[r][0] = fmaf(hv, bv.x, acc[r][0]);
                acc[r][1] = fmaf(hv, bv.y, acc[r][1]);
                acc[r][2] = fmaf(hv, bv.z, acc[r][2]);
                acc[r][3] = fmaf(hv, bv.w, acc[r][3]);
            }
        }
        __syncthreads();
    }
#pragma unroll
    for (int r = 0; r < 9; r++) {
        int c = ci + 16 * r;
        if (c < CH) {
            *(float4*)&d_o[(b * CH + c) * M_ + m0 + mi * 4] =
                make_float4(acc[r][0], acc[r][1], acc[r][2], acc[r][3]);
        }
    }
}

// ---------------- 13) net4 = gamma*o + net3 ----------------
__global__ void k_n4(const float* __restrict__ gamma_att) {
    int t = blockIdx.x * 256 + threadIdx.x;
    if (t >= B_ * CH * M_) return;
    d_n4[t] = fmaf(*gamma_att, d_o[t], d_net3[t]);
}

// ---------------- 14) y1 = relu(W1 @ net4 + b1)   (256x130) ----------------
__global__ void k_mlp1(const float* __restrict__ W, const float* __restrict__ bias) {
    int b = blockIdx.y, m0 = blockIdx.x * 64;
    __shared__ float In[CH][64];
    int tid = threadIdx.x;
    for (int e = tid; e < CH * 64; e += 256) {
        int k = e >> 6, i = e & 63;
        In[k][i] = d_n4[(b * CH + k) * M_ + m0 + i];
    }
    __syncthreads();
    int ml = tid & 63, rq = tid >> 6;
    for (int r = rq; r < MID; r += 4) {
        float acc = bias[r];
        const float* Wr = W + r * CH;
#pragma unroll 10
        for (int k = 0; k < CH; k++) acc = fmaf(Wr[k], In[k][ml], acc);
        d_y1[((size_t)b * MID + r) * M_ + m0 + ml] = fmaxf(acc, 0.f);
    }
}

// ---------------- 15) out = relu(W2 @ y1 + b2)   (128x256) ----------------
__global__ void k_mlp2(const float* __restrict__ W, const float* __restrict__ bias,
                       float* __restrict__ Out) {
    int b = blockIdx.y, m0 = blockIdx.x * 32;
    __shared__ float In[MID][32];
    int tid = threadIdx.x;
    for (int e = tid; e < MID * 32; e += 256) {
        int k = e >> 5, i = e & 31;
        In[k][i] = d_y1[((size_t)b * MID + k) * M_ + m0 + i];
    }
    __syncthreads();
    int ml = tid & 31, rq = tid >> 5;
    for (int r = rq; r < RO; r += 8) {
        float acc = bias[r];
        const float* Wr = W + r * MID;
#pragma unroll 16
        for (int k = 0; k < MID; k++) acc = fmaf(Wr[k], In[k][ml], acc);
        Out[((size_t)b * RO + r) * M_ + m0 + ml] = fmaxf(acc, 0.f);
    }
}

// ---------------- launch ----------------
extern "C" void kernel_launch(void* const* d_in, const int* in_sizes, int n_in,
                              void* d_out, int out_size) {
    const float* x    = (const float*)d_in[0];
    const float* Wec  = (const float*)d_in[1];
    const float* g_ec = (const float*)d_in[2];
    const float* b_ec = (const float*)d_in[3];
    const float* Wf   = (const float*)d_in[4];
    const float* bf   = (const float*)d_in[5];
    const float* gf   = (const float*)d_in[6];
    const float* betf = (const float*)d_in[7];
    const float* Wg   = (const float*)d_in[8];
    const float* bg   = (const float*)d_in[9];
    const float* gg   = (const float*)d_in[10];
    const float* betg = (const float*)d_in[11];
    const float* Wh   = (const float*)d_in[12];
    const float* bh   = (const float*)d_in[13];
    const float* gh   = (const float*)d_in[14];
    const float* beth = (const float*)d_in[15];
    const float* gam  = (const float*)d_in[16];
    const float* W1   = (const float*)d_in[17];
    const float* b1   = (const float*)d_in[18];
    const float* W2   = (const float*)d_in[19];
    const float* b2   = (const float*)d_in[20];
    float* out = (float*)d_out;

    k_sq    <<<16, 256>>>(x);
    k_negd  <<<dim3(16, 16, 4), 256>>>(x);
    k_topk  <<<B_ * N_, 256>>>();
    k_yb    <<<dim3(8, 16, 4), 256>>>(x, Wec);
    k_stats1<<<dim3(16, 4), 512>>>();
    k_red1  <<<2, 256>>>();
    k_edgemax<<<B_ * N_, 256>>>(g_ec, b_ec);
    k_grid  <<<64, 256>>>();
    k_fgh   <<<dim3(64, 4), 256>>>(Wf, bf, Wg, bg, Wh, bh);
    k_stats2<<<194, 256>>>();
    k_norm2 <<<(B_ * CF * M_ + 255) / 256, 256>>>(0, gf, betf);
    k_norm2 <<<(B_ * CF * M_ + 255) / 256, 256>>>(1, gg, betg);
    k_norm2 <<<(B_ * CH * M_ + 255) / 256, 256>>>(2, gh, beth);
    k_sgemm <<<dim3(64, 64, 4), 256>>>();
    k_softmax<<<B_ * M_, 256>>>();
    k_ogemm <<<dim3(64, 4), 256>>>();
    k_n4    <<<(B_ * CH * M_ + 255) / 256, 256>>>(gam);
    k_mlp1  <<<dim3(64, 4), 256>>>(W1, b1);
    k_mlp2  <<<dim3(128, 4), 256>>>(W2, b2, out);
}

// round 4
// speedup vs baseline: 1.0015x; 1.0015x over previous
#include <cuda_runtime.h>
#include <string.h>

// Problem constants
namespace {
constexpr int B_  = 4;
constexpr int C_  = 128;
constexpr int N_  = 1024;
constexpr int KNN = 20;
constexpr int M_  = 4096;   // N*UP
constexpr int OC  = 512;    // edge-conv out channels
constexpr int CH  = 130;    // net channels after grid concat
constexpr int CF  = 32;     // f/g channels
constexpr int MID = 256;    // W1 out
constexpr int RO  = 128;    // W2 out
}
#define EPS_ 1e-5f
#define NEGINF_ -3.4e38f

// ---- packed f32x2 FMA with defined-behavior punning ----
__device__ __forceinline__ float2 ffma2(float2 a, float2 b, float2 c) {
    unsigned long long au, bu, cu, du;
    memcpy(&au, &a, 8);
    memcpy(&bu, &b, 8);
    memcpy(&cu, &c, 8);
    asm("fma.rn.f32x2 %0, %1, %2, %3;" : "=l"(du) : "l"(au), "l"(bu), "l"(cu));
    float2 d;
    memcpy(&d, &du, 8);
    return d;
}
__device__ __forceinline__ float2 pack2(float x) { return make_float2(x, x); }

// ---- scratch (device globals; no allocations allowed) ----
__device__ float d_sq   [B_*N_];
__device__ float d_negd [B_*N_*N_];
__device__ int   d_idx  [B_*N_*KNN];
__device__ float d_Yt   [B_*N_*OC];    // [b][n][o]
__device__ float d_baset[B_*N_*OC];    // [b][n][o]
__device__ float d_st1p [2*64*OC];     // per-block partial sums (deterministic)
__device__ float d_st1  [2*OC];
__device__ float d_net3 [B_*CH*M_];    // [b][c][m]
__device__ float d_fr   [B_*CF*M_];
__device__ float d_gr   [B_*CF*M_];
__device__ float d_hr   [B_*CH*M_];
__device__ float d_st2  [2*(CF+CF+CH)];
__device__ float d_fn   [B_*CF*M_];
__device__ float d_gn   [B_*CF*M_];
__device__ float d_hn   [B_*CH*M_];
__device__ float d_s    [(size_t)B_*M_*M_];   // 268 MB attention matrix
__device__ float d_o    [B_*CH*M_];
__device__ float d_n4   [B_*CH*M_];
__device__ float d_y1   [B_*MID*M_];

// ---------------- 1) per-point squared norms ----------------
__global__ void k_sq(const float* __restrict__ x) {
    int t = blockIdx.x * 256 + threadIdx.x;      // B*N = 4096
    int b = t >> 10, n = t & 1023;
    const float* xb = x + b * C_ * N_ + n;
    float s = 0.f;
#pragma unroll 8
    for (int c = 0; c < C_; c++) { float v = xb[c * N_]; s = fmaf(v, v, s); }
    d_sq[t] = s;
}

// ---------------- 2) neg squared distance: 2 x^T x - sq_n - sq_m ----------------
__global__ void k_negd(const float* __restrict__ x) {
    int b = blockIdx.z;
    int n0 = blockIdx.y * 64, m0 = blockIdx.x * 64;
    __shared__ float As[32][64];
    __shared__ float Bs[32][64];
    int tid = threadIdx.x;
    const float* xb = x + b * C_ * N_;
    float2 acc[4][2] = {};
    for (int k0 = 0; k0 < C_; k0 += 32) {
        for (int e = tid; e < 32 * 64; e += 256) {
            int k = e >> 6, i = e & 63;
            As[k][i] = xb[(k0 + k) * N_ + n0 + i];
            Bs[k][i] = xb[(k0 + k) * N_ + m0 + i];
        }
        __syncthreads();
        int ty = tid >> 4, tx = tid & 15;
#pragma unroll
        for (int k = 0; k < 32; k++) {
            float2 b0 = *(const float2*)&Bs[k][tx * 4];
            float2 b1 = *(const float2*)&Bs[k][tx * 4 + 2];
#pragma unroll
            for (int i = 0; i < 4; i++) {
                float2 av = pack2(As[k][ty * 4 + i]);
                acc[i][0] = ffma2(av, b0, acc[i][0]);
                acc[i][1] = ffma2(av, b1, acc[i][1]);
            }
        }
        __syncthreads();
    }
    int ty = tid >> 4, tx = tid & 15;
#pragma unroll
    for (int i = 0; i < 4; i++) {
        int n = n0 + ty * 4 + i;
        float sn = d_sq[b * N_ + n];
        float4 o;
        o.x = 2.f * acc[i][0].x - sn - d_sq[b * N_ + m0 + tx * 4 + 0];
        o.y = 2.f * acc[i][0].y - sn - d_sq[b * N_ + m0 + tx * 4 + 1];
        o.z = 2.f * acc[i][1].x - sn - d_sq[b * N_ + m0 + tx * 4 + 2];
        o.w = 2.f * acc[i][1].y - sn - d_sq[b * N_ + m0 + tx * 4 + 3];
        *(float4*)&d_negd[(b * N_ + n) * N_ + m0 + tx * 4] = o;
    }
}

// ---------------- 3) top-k (k=20) per row, tie -> lower index ----------------
__global__ void k_topk() {
    int bn = blockIdx.x;                  // b*N + n
    __shared__ float vals[N_];
    __shared__ float rv[256];
    __shared__ int   ri[256];
    int tid = threadIdx.x;
    const float* row = &d_negd[(size_t)bn * N_];
    for (int i = tid; i < N_; i += 256) vals[i] = row[i];
    __syncthreads();
    for (int t = 0; t < KNN; t++) {
        float bv = NEGINF_; int bi = 0;
        for (int i = tid; i < N_; i += 256) {
            float v = vals[i];
            if (v > bv || (v == bv && i < bi)) { bv = v; bi = i; }
        }
        rv[tid] = bv; ri[tid] = bi;
        __syncthreads();
        for (int s = 128; s > 0; s >>= 1) {
            if (tid < s) {
                float v2 = rv[tid + s]; int i2 = ri[tid + s];
                if (v2 > rv[tid] || (v2 == rv[tid] && i2 < ri[tid])) { rv[tid] = v2; ri[tid] = i2; }
            }
            __syncthreads();
        }
        if (tid == 0) { d_idx[bn * KNN + t] = ri[0]; vals[ri[0]] = NEGINF_; }
        __syncthreads();
    }
}

// ---------------- 4) Y = Wa@x, base = (Wb-Wa)@x, both point-major ----------------
__global__ void k_yb(const float* __restrict__ x, const float* __restrict__ Wec) {
    int b = blockIdx.z;
    int n0 = blockIdx.y * 64;   // 16
    int o0 = blockIdx.x * 64;   // 8
    __shared__ float Xs[32][64];
    __shared__ float Was[32][64];
    __shared__ float Wbs[32][64];
    int tid = threadIdx.x;
    float2 a1[4][2] = {}, a2[4][2] = {};
    for (int k0 = 0; k0 < C_; k0 += 32) {
        for (int e = tid; e < 32 * 64; e += 256) {
            int k = e >> 6, i = e & 63;
            Xs[k][i] = x[b * C_ * N_ + (k0 + k) * N_ + n0 + i];
            float wa = Wec[(o0 + i) * 256 + k0 + k];
            float wb = Wec[(o0 + i) * 256 + 128 + k0 + k];
            Was[k][i] = wa;
            Wbs[k][i] = wb - wa;
        }
        __syncthreads();
        int ty = tid >> 4, tx = tid & 15;   // ty -> n, tx -> o
#pragma unroll
        for (int k = 0; k < 32; k++) {
            float2 wa0 = *(const float2*)&Was[k][tx * 4];
            float2 wa1 = *(const float2*)&Was[k][tx * 4 + 2];
            float2 wb0 = *(const float2*)&Wbs[k][tx * 4];
            float2 wb1 = *(const float2*)&Wbs[k][tx * 4 + 2];
#pragma unroll
            for (int i = 0; i < 4; i++) {
                float2 xv = pack2(Xs[k][ty * 4 + i]);
                a1[i][0] = ffma2(xv, wa0, a1[i][0]);
                a1[i][1] = ffma2(xv, wa1, a1[i][1]);
                a2[i][0] = ffma2(xv, wb0, a2[i][0]);
                a2[i][1] = ffma2(xv, wb1, a2[i][1]);
            }
        }
        __syncthreads();
    }
    int ty = tid >> 4, tx = tid & 15;
#pragma unroll
    for (int i = 0; i < 4; i++) {
        int n = n0 + ty * 4 + i;
        *(float4*)&d_Yt   [(b * N_ + n) * OC + o0 + tx * 4] =
            make_float4(a1[i][0].x, a1[i][0].y, a1[i][1].x, a1[i][1].y);
        *(float4*)&d_baset[(b * N_ + n) * OC + o0 + tx * 4] =
            make_float4(a2[i][0].x, a2[i][0].y, a2[i][1].x, a2[i][1].y);
    }
}

// ---------------- 5) BN stats for edge-conv (deterministic partials) ----------------
__global__ void k_stats1() {
    int b = blockIdx.y;
    int nc = blockIdx.x;            // 16 chunks of 64 points
    int p = b * 16 + nc;
    int o = threadIdx.x;            // 512
    __shared__ int sidx[64 * KNN];
    for (int e = threadIdx.x; e < 64 * KNN; e += 512)
        sidx[e] = d_idx[(b * N_ + nc * 64) * KNN + e];
    __syncthreads();
    float s = 0.f, ss = 0.f;
    for (int nn = 0; nn < 64; nn++) {
        int n = nc * 64 + nn;
        float bv = d_baset[(b * N_ + n) * OC + o];
#pragma unroll
        for (int k = 0; k < KNN; k++) {
            int j = sidx[nn * KNN + k];
            float v = d_Yt[(b * N_ + j) * OC + o] + bv;
            s += v; ss = fmaf(v, v, ss);
        }
    }
    d_st1p[p * OC + o] = s;
    d_st1p[(64 + p) * OC + o] = ss;
}

__global__ void k_red1() {
    int o = blockIdx.x * 256 + threadIdx.x;
    if (o >= OC) return;
    float s = 0.f, ss = 0.f;
    for (int p = 0; p < 64; p++) { s += d_st1p[p * OC + o]; ss += d_st1p[(64 + p) * OC + o]; }
    d_st1[o] = s; d_st1[OC + o] = ss;
}

// ---------------- 6) normalize + leaky + max over k, write reshaped net3 ----------------
__global__ void k_edgemax(const float* __restrict__ g_ec, const float* __restrict__ b_ec) {
    int bn = blockIdx.x;
    int b = bn >> 10, n = bn & 1023;
    __shared__ int sidx[KNN];
    int tid = threadIdx.x;
    if (tid < KNN) sidx[tid] = d_idx[bn * KNN + tid];
    __syncthreads();
    const float cnt = (float)(B_ * N_ * KNN);
    for (int o = tid; o < OC; o += 256) {
        float mean = d_st1[o] / cnt;
        float var  = d_st1[OC + o] / cnt - mean * mean;
        float sc = rsqrtf(var + EPS_) * g_ec[o];
        float sh = b_ec[o] - mean * sc;
        float bv = d_baset[bn * OC + o];
        float best = NEGINF_;
#pragma unroll
        for (int k = 0; k < KNN; k++) {
            float v = d_Yt[(b * N_ + sidx[k]) * OC + o] + bv;
            v = fmaf(v, sc, sh);
            v = v > 0.f ? v : 0.2f * v;
            best = fmaxf(best, v);
        }
        int u = o >> 7, c = o & 127;
        d_net3[(b * CH + c) * M_ + n * 4 + u] = best;
    }
}

__global__ void k_grid() {
    int t = blockIdx.x * 256 + threadIdx.x;   // B*M = 16384
    int b = t >> 12, m = t & 4095;
    int gi = m >> 10;
    float gx = (gi < 2) ? -0.2f : 0.2f;
    float gy = (gi & 1) ? 0.2f : -0.2f;
    d_net3[(b * CH + 128) * M_ + m] = gx;
    d_net3[(b * CH + 129) * M_ + m] = gy;
}

// ---------------- 7) f/g/h raw convs (K=130) ----------------
__global__ void k_fgh(const float* __restrict__ Wf, const float* __restrict__ bf,
                      const float* __restrict__ Wg, const float* __restrict__ bg,
                      const float* __restrict__ Wh, const float* __restrict__ bh) {
    int b = blockIdx.y, m0 = blockIdx.x * 64;
    __shared__ float In[CH][64];
    int tid = threadIdx.x;
    for (int e = tid; e < CH * 64; e += 256) {
        int k = e >> 6, i = e & 63;
        In[k][i] = d_net3[(b * CH + k) * M_ + m0 + i];
    }
    __syncthreads();
    int ml = tid & 63, rq = tid >> 6;
    for (int r = rq; r < 194; r += 4) {
        const float* W; float bias; float* outp;
        if (r < 32)      { W = Wf + r * CH;        bias = bf[r];      outp = &d_fr[(b * CF + r) * M_]; }
        else if (r < 64) { int c = r - 32; W = Wg + c * CH; bias = bg[c]; outp = &d_gr[(b * CF + c) * M_]; }
        else             { int c = r - 64; W = Wh + c * CH; bias = bh[c]; outp = &d_hr[(b * CH + c) * M_]; }
        float acc = bias;
#pragma unroll 10
        for (int k = 0; k < CH; k++) acc = fmaf(W[k], In[k][ml], acc);
        outp[m0 + ml] = acc;
    }
}

// ---------------- 8) BN stats for f/g/h (one block per channel) ----------------
__global__ void k_stats2() {
    int ch = blockIdx.x, tid = threadIdx.x;   // 194 channels
    __shared__ float r1[256], r2[256];
    float s = 0.f, ss = 0.f;
    for (int b = 0; b < B_; b++) {
        const float* p;
        if (ch < 32)      p = &d_fr[(b * CF + ch) * M_];
        else if (ch < 64) p = &d_gr[(b * CF + (ch - 32)) * M_];
        else              p = &d_hr[(b * CH + (ch - 64)) * M_];
        for (int m = tid; m < M_; m += 256) { float v = p[m]; s += v; ss = fmaf(v, v, ss); }
    }
    r1[tid] = s; r2[tid] = ss;
    __syncthreads();
    for (int st = 128; st > 0; st >>= 1) {
        if (tid < st) { r1[tid] += r1[tid + st]; r2[tid] += r2[tid + st]; }
        __syncthreads();
    }
    if (tid == 0) { d_st2[ch] = r1[0]; d_st2[194 + ch] = r2[0]; }
}

// ---------------- 9) normalize + relu (sel: 0=f, 1=g, 2=h) ----------------
__global__ void k_norm2(int sel, const float* __restrict__ gamma, const float* __restrict__ beta) {
    int t = blockIdx.x * 256 + threadIdx.x;
    int Cdim = (sel == 2) ? CH : CF;
    int total = B_ * Cdim * M_;
    if (t >= total) return;
    int c = (t / M_) % Cdim;
    int off = (sel == 0) ? 0 : (sel == 1) ? 32 : 64;
    const float cntf = (float)(B_ * M_);
    float mean = d_st2[off + c] / cntf;
    float var  = d_st2[194 + off + c] / cntf - mean * mean;
    float sc = rsqrtf(var + EPS_) * gamma[c];
    float sh = beta[c] - mean * sc;
    const float* raw = (sel == 0) ? d_fr : (sel == 1) ? d_gr : d_hr;
    float* outp      = (sel == 0) ? d_fn : (sel == 1) ? d_gn : d_hn;
    outp[t] = fmaxf(fmaf(raw[t], sc, sh), 0.f);
}

// ---------------- 10) s[b,m,n] = sum_c g[c,m] f[c,n]  (K=32) ----------------
__global__ void k_sgemm() {
    int b = blockIdx.z;
    int m0 = blockIdx.y * 64, n0 = blockIdx.x * 64;
    __shared__ float Gs[CF][64];
    __shared__ float Fs[CF][64];
    int tid = threadIdx.x;
    for (int e = tid; e < CF * 64; e += 256) {
        int k = e >> 6, i = e & 63;
        Gs[k][i] = d_gn[(b * CF + k) * M_ + m0 + i];
        Fs[k][i] = d_fn[(b * CF + k) * M_ + n0 + i];
    }
    __syncthreads();
    int ty = tid >> 4, tx = tid & 15;
    float2 acc[4][2] = {};
#pragma unroll
    for (int k = 0; k < CF; k++) {
        float2 f0 = *(const float2*)&Fs[k][tx * 4];
        float2 f1 = *(const float2*)&Fs[k][tx * 4 + 2];
#pragma unroll
        for (int i = 0; i < 4; i++) {
            float2 gv = pack2(Gs[k][ty * 4 + i]);
            acc[i][0] = ffma2(gv, f0, acc[i][0]);
            acc[i][1] = ffma2(gv, f1, acc[i][1]);
        }
    }
#pragma unroll
    for (int i = 0; i < 4; i++) {
        int m = m0 + ty * 4 + i;
        *(float4*)&d_s[((size_t)(b * M_ + m)) * M_ + n0 + tx * 4] =
            make_float4(acc[i][0].x, acc[i][0].y, acc[i][1].x, acc[i][1].y);
    }
}

// ---------------- 11) row softmax (axis=2), in place ----------------
__global__ void k_softmax() {
    int bm = blockIdx.x;     // B*M rows
    __shared__ float row[M_];
    __shared__ float red[256];
    float* src = &d_s[(size_t)bm * M_];
    int tid = threadIdx.x;
    float mx = NEGINF_;
    for (int i = tid; i < M_; i += 256) { float v = src[i]; row[i] = v; mx = fmaxf(mx, v); }
    red[tid] = mx;
    __syncthreads();
    for (int s = 128; s > 0; s >>= 1) { if (tid < s) red[tid] = fmaxf(red[tid], red[tid + s]); __syncthreads(); }
    mx = red[0];
    __syncthreads();
    float sum = 0.f;
    for (int i = tid; i < M_; i += 256) { float e = __expf(row[i] - mx); row[i] = e; sum += e; }
    red[tid] = sum;
    __syncthreads();
    for (int s = 128; s > 0; s >>= 1) { if (tid < s) red[tid] += red[tid + s]; __syncthreads(); }
    float inv = 1.f / red[0];
    __syncthreads();
    for (int i = tid; i < M_; i += 256) src[i] = row[i] * inv;
}

// ---------------- 12) o[b,c,m] = sum_j h[c,j] * beta[j,m]  (the FLOP wall) ----------------
__global__ void k_ogemm() {
    int b = blockIdx.y;
    int m0 = blockIdx.x * 64;
    __shared__ float Bs[16][64];
    __shared__ float Hs[16][144];
    int tid = threadIdx.x;
    int mi = tid & 15, ci = tid >> 4;   // mi -> 4 m's, ci + 16r -> c
    float2 acc[9][2] = {};
    for (int j0 = 0; j0 < M_; j0 += 16) {
        {
            int k = tid >> 4, c4 = tid & 15;
            *(float4*)&Bs[k][c4 * 4] =
                *(const float4*)&d_s[((size_t)(b * M_ + j0 + k)) * M_ + m0 + c4 * 4];
        }
        for (int e = tid; e < 16 * 144; e += 256) {
            int c = e >> 4, k = e & 15;
            Hs[k][c] = (c < CH) ? d_hn[(b * CH + c) * M_ + j0 + k] : 0.f;
        }
        __syncthreads();
#pragma unroll
        for (int k = 0; k < 16; k++) {
            float2 bv0 = *(const float2*)&Bs[k][mi * 4];
            float2 bv1 = *(const float2*)&Bs[k][mi * 4 + 2];
#pragma unroll
            for (int r = 0; r < 9; r++) {
                float2 hv = pack2(Hs[k][ci + 16 * r]);
                acc[r][0] = ffma2(hv, bv0, acc[r][0]);
                acc[r][1] = ffma2(hv, bv1, acc[r][1]);
            }
        }
        __syncthreads();
    }
#pragma unroll
    for (int r = 0; r < 9; r++) {
        int c = ci + 16 * r;
        if (c < CH) {
            *(float4*)&d_o[(b * CH + c) * M_ + m0 + mi * 4] =
                make_float4(acc[r][0].x, acc[r][0].y, acc[r][1].x, acc[r][1].y);
        }
    }
}

// ---------------- 13) net4 = gamma*o + net3 ----------------
__global__ void k_n4(const float* __restrict__ gamma_att) {
    int t = blockIdx.x * 256 + threadIdx.x;
    if (t >= B_ * CH * M_) return;
    d_n4[t] = fmaf(*gamma_att, d_o[t], d_net3[t]);
}

// ---------------- 14) y1 = relu(W1 @ net4 + b1)   (256x130) ----------------
__global__ void k_mlp1(const float* __restrict__ W, const float* __restrict__ bias) {
    int b = blockIdx.y, m0 = blockIdx.x * 64;
    __shared__ float In[CH][64];
    int tid = threadIdx.x;
    for (int e = tid; e < CH * 64; e += 256) {
        int k = e >> 6, i = e & 63;
        In[k][i] = d_n4[(b * CH + k) * M_ + m0 + i];
    }
    __syncthreads();
    int ml = tid & 63, rq = tid >> 6;
    for (int r = rq; r < MID; r += 4) {
        float acc = bias[r];
        const float* Wr = W + r * CH;
#pragma unroll 10
        for (int k = 0; k < CH; k++) acc = fmaf(Wr[k], In[k][ml], acc);
        d_y1[((size_t)b * MID + r) * M_ + m0 + ml] = fmaxf(acc, 0.f);
    }
}

// ---------------- 15) out = relu(W2 @ y1 + b2)   (128x256) ----------------
__global__ void k_mlp2(const float* __restrict__ W, const float* __restrict__ bias,
                       float* __restrict__ Out) {
    int b = blockIdx.y, m0 = blockIdx.x * 32;
    __shared__ float In[MID][32];
    int tid = threadIdx.x;
    for (int e = tid; e < MID * 32; e += 256) {
        int k = e >> 5, i = e & 31;
        In[k][i] = d_y1[((size_t)b * MID + k) * M_ + m0 + i];
    }
    __syncthreads();
    int ml = tid & 31, rq = tid >> 5;
    for (int r = rq; r < RO; r += 8) {
        float acc = bias[r];
        const float* Wr = W + r * MID;
#pragma unroll 16
        for (int k = 0; k < MID; k++) acc = fmaf(Wr[k], In[k][ml], acc);
        Out[((size_t)b * RO + r) * M_ + m0 + ml] = fmaxf(acc, 0.f);
    }
}

// ---------------- launch ----------------
extern "C" void kernel_launch(void* const* d_in, const int* in_sizes, int n_in,
                              void* d_out, int out_size) {
    const float* x    = (const float*)d_in[0];
    const float* Wec  = (const float*)d_in[1];
    const float* g_ec = (const float*)d_in[2];
    const float* b_ec = (const float*)d_in[3];
    const float* Wf   = (const float*)d_in[4];
    const float* bf   = (const float*)d_in[5];
    const float* gf   = (const float*)d_in[6];
    const float* betf = (const float*)d_in[7];
    const float* Wg   = (const float*)d_in[8];
    const float* bg   = (const float*)d_in[9];
    const float* gg   = (const float*)d_in[10];
    const float* betg = (const float*)d_in[11];
    const float* Wh   = (const float*)d_in[12];
    const float* bh   = (const float*)d_in[13];
    const float* gh   = (const float*)d_in[14];
    const float* beth = (const float*)d_in[15];
    const float* gam  = (const float*)d_in[16];
    const float* W1   = (const float*)d_in[17];
    const float* b1   = (const float*)d_in[18];
    const float* W2   = (const float*)d_in[19];
    const float* b2   = (const float*)d_in[20];
    float* out = (float*)d_out;

    k_sq    <<<16, 256>>>(x);
    k_negd  <<<dim3(16, 16, 4), 256>>>(x);
    k_topk  <<<B_ * N_, 256>>>();
    k_yb    <<<dim3(8, 16, 4), 256>>>(x, Wec);
    k_stats1<<<dim3(16, 4), 512>>>();
    k_red1  <<<2, 256>>>();
    k_edgemax<<<B_ * N_, 256>>>(g_ec, b_ec);
    k_grid  <<<64, 256>>>();
    k_fgh   <<<dim3(64, 4), 256>>>(Wf, bf, Wg, bg, Wh, bh);
    k_stats2<<<194, 256>>>();
    k_norm2 <<<(B_ * CF * M_ + 255) / 256, 256>>>(0, gf, betf);
    k_norm2 <<<(B_ * CF * M_ + 255) / 256, 256>>>(1, gg, betg);
    k_norm2 <<<(B_ * CH * M_ + 255) / 256, 256>>>(2, gh, beth);
    k_sgemm <<<dim3(64, 64, 4), 256>>>();
    k_softmax<<<B_ * M_, 256>>>();
    k_ogemm <<<dim3(64, 4), 256>>>();
    k_n4    <<<(B_ * CH * M_ + 255) / 256, 256>>>(gam);
    k_mlp1  <<<dim3(64, 4), 256>>>(W1, b1);
    k_mlp2  <<<dim3(128, 4), 256>>>(W2, b2, out);
}